// round 3
// baseline (speedup 1.0000x reference)
#include <cuda_runtime.h>
#include <cuda_bf16.h>

#define NBINS 36
#define PS 32
#define BLK 128
#define HSTRIDE 132              // RMW bank = t (conflict-free); LDS.128 reads spread 4l%32
#define TWO_PI_F 6.2831855f      // f32(2*pi)
#define PI_F     3.1415927f      // f32(pi)

typedef unsigned long long ull;

__device__ __forceinline__ ull f2_add(ull a, ull b) {
    ull r; asm("add.rn.f32x2 %0,%1,%2;" : "=l"(r) : "l"(a), "l"(b)); return r;
}
__device__ __forceinline__ void unpackf2(ull v, float& a, float& b) {
    asm("mov.b64 {%0,%1},%2;" : "=f"(a), "=f"(b) : "l"(v));
}
__device__ __forceinline__ float rsq_approx(float x) {
    float r; asm("rsqrt.approx.f32 %0,%1;" : "=f"(r) : "f"(x)); return r;
}

__global__ __launch_bounds__(BLK, 10)
void OrientationFinder_83193516523885_kernel(
    const float* __restrict__ x,
    const float* __restrict__ gxw,
    const float* __restrict__ gyw,
    const float* __restrict__ smw,
    const float* __restrict__ gk,
    float* __restrict__ out)
{
    __shared__ __align__(16) float hist[NBINS * HSTRIDE]; // 18.6 KB, per-thread columns
    __shared__ float part[144];                           // [quarter][bin]
    __shared__ float binsum[40];

    const int t = threadIdx.x;
    const long long base = (long long)blockIdx.x * (PS * PS);
    const int r  = t >> 2;            // row 0..31
    const int c0 = (t & 3) << 3;      // col 0,8,16,24
    const int rm = (r > 0) ? r - 1 : 0;
    const int rp = (r < PS - 1) ? r + 1 : PS - 1;

    // ---- issue all global loads up front (own strip + neighbor rows, L1-resident) ----
    const float* px = x + base;
    const float4* pc = (const float4*)(px + r  * PS + c0);
    const float4* pu = (const float4*)(px + rm * PS + c0);
    const float4* pd = (const float4*)(px + rp * PS + c0);
    const float4* pg = (const float4*)(gk + r * PS + c0);
    float4 v0 = pc[0], v1 = pc[1];
    float4 u0 = pu[0], u1 = pu[1];
    float4 d0 = pd[0], d1 = pd[1];
    float4 g0 = pg[0], g1 = pg[1];
    float left  = (c0 > 0)      ? __ldg(px + r * PS + c0 - 1) : v0.x;   // edge replicate
    float right = (c0 + 8 < PS) ? __ldg(px + r * PS + c0 + 8) : v1.w;

    // ---- zero hist (flat float4: 1188 vectors over 128 threads) ----
    {
        float4 z = make_float4(0.f, 0.f, 0.f, 0.f);
        float4* hz = (float4*)hist;
        #pragma unroll
        for (int i = 0; i < 9; ++i) hz[t + i * BLK] = z;
        if (t < 1188 - 9 * BLK) hz[t + 9 * BLK] = z;
    }
    const float w0x = gxw[0], w1x = gxw[1], w2x = gxw[2];
    const float w0y = gyw[0], w1y = gyw[1], w2y = gyw[2];
    __syncthreads();   // hist zeroed before any RMW; placed early = minimal skew

    float sa[10] = {left, v0.x, v0.y, v0.z, v0.w, v1.x, v1.y, v1.z, v1.w, right};
    float uu[8]  = {u0.x, u0.y, u0.z, u0.w, u1.x, u1.y, u1.z, u1.w};
    float dd[8]  = {d0.x, d0.y, d0.z, d0.w, d1.x, d1.y, d1.z, d1.w};
    float gg[8]  = {g0.x, g0.y, g0.z, g0.w, g1.x, g1.y, g1.z, g1.w};

    // strip-level skip: gk == 0 over the whole strip -> no contribution at all
    float gsum = (g0.x + g0.y + g0.z + g0.w) + (g1.x + g1.y + g1.z + g1.w);

    if (gsum > 0.0f) {
        int   bb[8];
        float ww[8];

        // ---- phase A: 8 independent pixel chains (atan2/div latencies overlap) ----
        #pragma unroll
        for (int i = 0; i < 8; ++i) {
            // exact reference association: (w0*a + w1*b) + w2*c, rn, no contraction
            float gx = __fadd_rn(__fadd_rn(__fmul_rn(w0x, sa[i]),
                                           __fmul_rn(w1x, sa[i + 1])),
                                 __fmul_rn(w2x, sa[i + 2]));
            float gy = __fadd_rn(__fadd_rn(__fmul_rn(w0y, uu[i]),
                                           __fmul_rn(w1y, sa[i + 1])),
                                 __fmul_rn(w2y, dd[i]));
            float s = __fadd_rn(__fadd_rn(__fmul_rn(gx, gx), __fmul_rn(gy, gy)),
                                1e-10f);
            // mag = sqrt(s)*gk via s*rsqrt(s) (continuous-effect approx, proven passing)
            float m = __fmul_rn(__fmul_rn(s, rsq_approx(s)), gg[i]);
            ww[i] = 0.0f;
            bb[i] = 0;
            if (m > 0.001f) {
                float o = atan2f(gy, gx);                 // bit-exact libdevice path
                if (o < 0.0f) o = __fadd_rn(o, TWO_PI_F); // jnp.mod(ori, 2pi)
                float ob  = __fdiv_rn(__fmul_rn(36.0f, o), TWO_PI_F);
                float bf  = floorf(ob);
                float wo1 = __fsub_rn(ob, bf);
                int   b   = (int)bf;
                if (b > NBINS - 1) b -= NBINS;            // ob == 36.0 edge
                bb[i] = b;
                ww[i] = __fmul_rn(__fsub_rn(1.0f, wo1), m);
            }
        }

        // ---- phase B: scatter (private column t, no atomics, no conflicts) ----
        float* hcol = hist + t;
        #pragma unroll
        for (int i = 0; i < 8; ++i) {
            if (ww[i] > 0.0f)
                hcol[bb[i] * HSTRIDE] = __fadd_rn(hcol[bb[i] * HSTRIDE], ww[i]);
        }
    }

    __syncthreads();

    // ---- stage 1: unit = (bin, 32-col quarter); bin = lane ----
    {
        const int lane = t & 31;
        const int q    = t >> 5;
        {
            const ulonglong2* p = (const ulonglong2*)(hist + lane * HSTRIDE + q * 32);
            ulonglong2 e = p[0];
            ull a0 = e.x, a1 = e.y;
            #pragma unroll
            for (int j = 1; j < 8; ++j) {
                e = p[j];
                a0 = f2_add(a0, e.x);
                a1 = f2_add(a1, e.y);
            }
            a0 = f2_add(a0, a1);
            float fa, fb; unpackf2(a0, fa, fb);
            part[q * 36 + lane] = fa + fb;
        }
        if (lane < 4) {   // bins 32..35
            const int b = 32 + lane;
            const ulonglong2* p = (const ulonglong2*)(hist + b * HSTRIDE + q * 32);
            ulonglong2 e = p[0];
            ull a0 = e.x, a1 = e.y;
            #pragma unroll
            for (int j = 1; j < 8; ++j) {
                e = p[j];
                a0 = f2_add(a0, e.x);
                a1 = f2_add(a1, e.y);
            }
            a0 = f2_add(a0, a1);
            float fa, fb; unpackf2(a0, fa, fb);
            part[q * 36 + b] = fa + fb;
        }
    }
    __syncthreads();

    if (t < NBINS) {
        float v = part[t] + part[36 + t] + part[72 + t] + part[108 + t];
        binsum[t] = v * 0.0009765625f;   // /1024 exact
    }
    __syncthreads();

    // ---- smoothing + first-index argmax (warp 0) ----
    if (t < 32) {
        const int lane = t;
        const float m0 = smw[0], m1 = smw[1], m2 = smw[2];
        float hm = (lane > 0) ? binsum[lane - 1] : 0.0f;
        float hc = binsum[lane];
        float hp = binsum[lane + 1];
        float v1 = __fadd_rn(__fadd_rn(__fmul_rn(m0, hm), __fmul_rn(m1, hc)),
                             __fmul_rn(m2, hp));
        int i1 = lane;
        if (lane < 4) {
            int b2 = 32 + lane;
            float hm2 = binsum[b2 - 1];
            float hc2 = binsum[b2];
            float hp2 = (b2 < NBINS - 1) ? binsum[b2 + 1] : 0.0f;
            float v2 = __fadd_rn(__fadd_rn(__fmul_rn(m0, hm2), __fmul_rn(m1, hc2)),
                                 __fmul_rn(m2, hp2));
            if (v2 > v1) { v1 = v2; i1 = b2; }
        }
        #pragma unroll
        for (int off = 16; off > 0; off >>= 1) {
            float ov = __shfl_xor_sync(0xffffffffu, v1, off);
            int   oi = __shfl_xor_sync(0xffffffffu, i1, off);
            if (ov > v1 || (ov == v1 && oi < i1)) { v1 = ov; i1 = oi; }
        }
        if (lane == 0) {
            float fi = (float)i1;
            float tt = __fdiv_rn(__fmul_rn(TWO_PI_F, fi), 36.0f);
            out[blockIdx.x] = -__fsub_rn(tt, PI_F);
        }
    }
}

extern "C" void kernel_launch(void* const* d_in, const int* in_sizes, int n_in,
                              void* d_out, int out_size)
{
    const float* x   = (const float*)d_in[0];
    const float* gxw = (const float*)d_in[1];
    const float* gyw = (const float*)d_in[2];
    const float* smw = (const float*)d_in[3];
    const float* gk  = (const float*)d_in[4];
    float* out = (float*)d_out;

    int B = in_sizes[0] / (PS * PS);
    OrientationFinder_83193516523885_kernel<<<B, BLK>>>(x, gxw, gyw, smw, gk, out);
}

// round 4
// speedup vs baseline: 1.1610x; 1.1610x over previous
#include <cuda_runtime.h>
#include <cuda_bf16.h>

#define NBINS 36
#define PS 32
#define BLK 128
#define TWO_PI_F 6.2831855f      // f32(2*pi)
#define PI_F     3.1415927f      // f32(pi)
#define FULLM 0xffffffffu

__device__ __forceinline__ float rsq_approx(float x) {
    float r; asm("rsqrt.approx.f32 %0,%1;" : "=f"(r) : "f"(x)); return r;
}

__global__ __launch_bounds__(BLK, 6)   // cap regs ~85: no spills, 6 CTAs/SM
void OrientationFinder_83193516523885_kernel(
    const float* __restrict__ x,
    const float* __restrict__ gxw,
    const float* __restrict__ gyw,
    const float* __restrict__ smw,
    const float* __restrict__ gk,
    float* __restrict__ out,
    int B)
{
    __shared__ __align__(16) float gksm[PS * 36];          // gk, padded stride 36
    __shared__ __align__(16) float hist4[4][NBINS * 32];   // per-warp hist (tile overlaid)

    const int t = threadIdx.x;
    const int w = t >> 5, l = t & 31;

    // ---- cooperative gk staging (rows padded to 36 floats; conflict-free reads later) ----
    {
        const float4* g4 = (const float4*)gk;
        #pragma unroll
        for (int j = 0; j < 2; ++j) {
            int m = t + BLK * j;                 // float4 index 0..255
            float4 v = g4[m];
            *(float4*)&gksm[(m >> 3) * 36 + ((m & 7) << 2)] = v;
        }
    }

    const long long p = (long long)blockIdx.x * 4 + w;     // one warp = one patch
    float* hist = hist4[w];

    // ---- coalesced global load of own patch (warp-linear order) ----
    float4 vb[8];
    if (p < B) {
        const float4* xv = (const float4*)(x + p * (PS * PS));
        #pragma unroll
        for (int j = 0; j < 8; ++j) vb[j] = xv[l + 32 * j];
    }
    const float w0x = gxw[0], w1x = gxw[1], w2x = gxw[2];
    const float w0y = gyw[0], w1y = gyw[1], w2y = gyw[2];
    const float m0 = smw[0], m1 = smw[1], m2 = smw[2];

    __syncthreads();            // gksm visible; the ONLY block-wide sync

    if (p >= (long long)B) return;

    // ---- redistribute to row-major tile (overlaid on hist; tile == 1152 floats) ----
    float* tile = hist;         // stride-36 rows
    #pragma unroll
    for (int j = 0; j < 8; ++j) {
        int m = l + 32 * j;
        *(float4*)&tile[(m >> 3) * 36 + ((m & 7) << 2)] = vb[j];
    }
    __syncwarp();

    float c[32];                // lane l holds row l entirely
    #pragma unroll
    for (int j = 0; j < 8; ++j) {
        float4 v = *(const float4*)&tile[l * 36 + 4 * j];
        c[4*j] = v.x; c[4*j+1] = v.y; c[4*j+2] = v.z; c[4*j+3] = v.w;
    }
    __syncwarp();

    // ---- zero hist (overwrites tile; 288 float4 over 32 lanes) ----
    {
        float4 z = make_float4(0.f, 0.f, 0.f, 0.f);
        #pragma unroll
        for (int j = 0; j < 9; ++j)
            *(float4*)&hist[(l + 32 * j) << 2] = z;
    }
    __syncwarp();

    // ---- main loop: 4 chunks x 8 pixels; up/dn via shfl (edge-replicate free) ----
    #pragma unroll
    for (int k = 0; k < 4; ++k) {
        float4 ga = *(const float4*)&gksm[l * 36 + 8 * k];
        float4 gb = *(const float4*)&gksm[l * 36 + 8 * k + 4];
        float gg[8] = {ga.x, ga.y, ga.z, ga.w, gb.x, gb.y, gb.z, gb.w};
        int bb[8]; float ww[8];
        #pragma unroll
        for (int i = 0; i < 8; ++i) {
            const int q = 8 * k + i;
            float up = __shfl_up_sync(FULLM, c[q], 1);    // lane 0 -> own (replicate)
            float dn = __shfl_down_sync(FULLM, c[q], 1);  // lane 31 -> own (replicate)
            float lf = (q > 0)  ? c[q - 1] : c[0];
            float rt = (q < 31) ? c[q + 1] : c[31];
            // exact reference association, rn, no contraction
            float gx = __fadd_rn(__fadd_rn(__fmul_rn(w0x, lf),
                                           __fmul_rn(w1x, c[q])),
                                 __fmul_rn(w2x, rt));
            float gy = __fadd_rn(__fadd_rn(__fmul_rn(w0y, up),
                                           __fmul_rn(w1y, c[q])),
                                 __fmul_rn(w2y, dn));
            float s  = __fadd_rn(__fadd_rn(__fmul_rn(gx, gx), __fmul_rn(gy, gy)),
                                 1e-10f);
            float m  = __fmul_rn(__fmul_rn(s, rsq_approx(s)), gg[i]);
            ww[i] = 0.f; bb[i] = 0;
            if (m > 0.001f) {
                float o = atan2f(gy, gx);                  // bit-exact libdevice path
                if (o < 0.f) o = __fadd_rn(o, TWO_PI_F);   // jnp.mod(ori, 2pi)
                float ob = __fdiv_rn(__fmul_rn(36.f, o), TWO_PI_F);
                float bf = floorf(ob);
                int b = (int)bf;
                if (b > NBINS - 1) b -= NBINS;             // ob == 36.0 edge
                bb[i] = b;
                ww[i] = __fmul_rn(__fsub_rn(1.f, __fsub_rn(ob, bf)), m);
            }
        }
        // scatter: addr = bin*32 + lane -> bank = lane, conflict-free for ANY bin
        #pragma unroll
        for (int i = 0; i < 8; ++i) {
            if (ww[i] > 0.f) {
                int a = bb[i] * 32 + l;
                hist[a] = __fadd_rn(hist[a], ww[i]);
            }
        }
    }
    __syncwarp();

    // ---- per-lane bin sums (diagonal reads: bank = (l+cc)&31, conflict-free) ----
    float s = 0.f, e = 0.f;
    #pragma unroll
    for (int cc = 0; cc < 32; ++cc)
        s = __fadd_rn(s, hist[(l << 5) + ((l + cc) & 31)]);
    if (l < 4) {
        #pragma unroll
        for (int cc = 0; cc < 32; ++cc)
            e = __fadd_rn(e, hist[((32 + l) << 5) + ((l + cc) & 31)]);
    }
    s = __fmul_rn(s, 0.0009765625f);    // /1024 exact
    e = __fmul_rn(e, 0.0009765625f);

    // ---- smoothing + first-index argmax, fully in-warp ----
    float hm  = __shfl_up_sync(FULLM, s, 1);
    float hp  = __shfl_down_sync(FULLM, s, 1);
    float e0  = __shfl_sync(FULLM, e, 0);
    float s31 = __shfl_sync(FULLM, s, 31);
    float em  = __shfl_up_sync(FULLM, e, 1);
    float ep  = __shfl_down_sync(FULLM, e, 1);
    if (l == 0)  hm = 0.f;              // zero pad left
    if (l == 31) hp = e0;               // h[32]
    float v1 = __fadd_rn(__fadd_rn(__fmul_rn(m0, hm), __fmul_rn(m1, s)),
                         __fmul_rn(m2, hp));
    int i1 = l;
    if (l < 4) {                        // bins 32..35 on lanes 0..3
        float hm2 = (l == 0) ? s31 : em;
        float hp2 = (l == 3) ? 0.f : ep;   // zero pad right
        float v2 = __fadd_rn(__fadd_rn(__fmul_rn(m0, hm2), __fmul_rn(m1, e)),
                             __fmul_rn(m2, hp2));
        if (v2 > v1) { v1 = v2; i1 = 32 + l; }   // tie keeps smaller index
    }
    #pragma unroll
    for (int off = 16; off > 0; off >>= 1) {
        float ov = __shfl_xor_sync(FULLM, v1, off);
        int   oi = __shfl_xor_sync(FULLM, i1, off);
        if (ov > v1 || (ov == v1 && oi < i1)) { v1 = ov; i1 = oi; }
    }
    if (l == 0) {
        float fi = (float)i1;
        out[p] = -__fsub_rn(__fdiv_rn(__fmul_rn(TWO_PI_F, fi), 36.f), PI_F);
    }
}

extern "C" void kernel_launch(void* const* d_in, const int* in_sizes, int n_in,
                              void* d_out, int out_size)
{
    const float* x   = (const float*)d_in[0];
    const float* gxw = (const float*)d_in[1];
    const float* gyw = (const float*)d_in[2];
    const float* smw = (const float*)d_in[3];
    const float* gk  = (const float*)d_in[4];
    float* out = (float*)d_out;

    int B = in_sizes[0] / (PS * PS);
    int grid = (B + 3) / 4;
    OrientationFinder_83193516523885_kernel<<<grid, BLK>>>(x, gxw, gyw, smw, gk, out, B);
}

// round 5
// speedup vs baseline: 1.3213x; 1.1381x over previous
#include <cuda_runtime.h>
#include <cuda_bf16.h>

#define NBINS 36
#define PS 32
#define BLK 128
#define TWO_PI_F 6.2831855f      // f32(2*pi)
#define PI_F     3.1415927f      // f32(pi)
#define FULLM 0xffffffffu

__device__ __forceinline__ float sqrt_approx(float x) {
    float r; asm("sqrt.approx.f32 %0,%1;" : "=f"(r) : "f"(x)); return r;
}

__global__ __launch_bounds__(BLK, 8)   // 64-reg cap, 8 CTAs/SM (smem 23KB -> fits)
void OrientationFinder_83193516523885_kernel(
    const float* __restrict__ x,
    const float* __restrict__ gxw,
    const float* __restrict__ gyw,
    const float* __restrict__ smw,
    const float* __restrict__ gk,
    float* __restrict__ out,
    int B)
{
    __shared__ __align__(16) float gksm[PS * 36];          // gk, padded stride 36
    __shared__ __align__(16) float hist4[4][NBINS * 32];   // per-warp hist (tile overlaid)

    const int t = threadIdx.x;
    const int w = t >> 5, l = t & 31;

    // ---- cooperative gk staging ----
    {
        const float4* g4 = (const float4*)gk;
        #pragma unroll
        for (int j = 0; j < 2; ++j) {
            int m = t + BLK * j;
            float4 v = g4[m];
            *(float4*)&gksm[(m >> 3) * 36 + ((m & 7) << 2)] = v;
        }
    }

    const long long p = (long long)blockIdx.x * 4 + w;     // one warp = one patch
    float* hist = hist4[w];

    // ---- coalesced global load of own patch ----
    float4 vb[8];
    if (p < B) {
        const float4* xv = (const float4*)(x + p * (PS * PS));
        #pragma unroll
        for (int j = 0; j < 8; ++j) vb[j] = xv[l + 32 * j];
    }
    const float w0x = gxw[0], w1x = gxw[1], w2x = gxw[2];
    const float w0y = gyw[0], w1y = gyw[1], w2y = gyw[2];
    const float m0 = smw[0], m1 = smw[1], m2 = smw[2];
    // uniform fast-path flags: middle taps are 0.0 in this dataset (bit-safe:
    // w1*b = +-0.0 only perturbs zero-signs, all masked by the m>0.001 keep)
    const bool fx = (w1x == 0.0f);
    const bool fy = (w1y == 0.0f);

    __syncthreads();            // gksm visible; only block-wide sync

    if (p >= (long long)B) return;

    // ---- redistribute to row-major tile (overlaid on hist) ----
    float* tile = hist;         // stride-36 rows
    #pragma unroll
    for (int j = 0; j < 8; ++j) {
        int m = l + 32 * j;
        *(float4*)&tile[(m >> 3) * 36 + ((m & 7) << 2)] = vb[j];
    }
    __syncwarp();

    float c[32];                // lane l holds row l
    #pragma unroll
    for (int j = 0; j < 8; ++j) {
        float4 v = *(const float4*)&tile[l * 36 + 4 * j];
        c[4*j] = v.x; c[4*j+1] = v.y; c[4*j+2] = v.z; c[4*j+3] = v.w;
    }
    __syncwarp();

    // ---- zero hist (overwrites tile) ----
    {
        float4 z = make_float4(0.f, 0.f, 0.f, 0.f);
        #pragma unroll
        for (int j = 0; j < 9; ++j)
            *(float4*)&hist[(l + 32 * j) << 2] = z;
    }
    __syncwarp();

    // ---- main loop: immediate per-pixel RMW (bank = lane, conflict-free) ----
    #pragma unroll
    for (int k = 0; k < 4; ++k) {
        float4 ga = *(const float4*)&gksm[l * 36 + 8 * k];
        float4 gb = *(const float4*)&gksm[l * 36 + 8 * k + 4];
        float gg[8] = {ga.x, ga.y, ga.z, ga.w, gb.x, gb.y, gb.z, gb.w};
        #pragma unroll
        for (int i = 0; i < 8; ++i) {
            const int q = 8 * k + i;
            float up = __shfl_up_sync(FULLM, c[q], 1);    // lane 0 -> self (replicate)
            float dn = __shfl_down_sync(FULLM, c[q], 1);  // lane 31 -> self
            float lf = (q > 0)  ? c[q - 1] : c[0];
            float rt = (q < 31) ? c[q + 1] : c[31];
            // fast 2-term gradients; uniform never-taken fallback keeps generality
            float gx = __fadd_rn(__fmul_rn(w0x, lf), __fmul_rn(w2x, rt));
            if (!fx) gx = __fadd_rn(__fadd_rn(__fmul_rn(w0x, lf),
                                              __fmul_rn(w1x, c[q])),
                                    __fmul_rn(w2x, rt));
            float gy = __fadd_rn(__fmul_rn(w0y, up), __fmul_rn(w2y, dn));
            if (!fy) gy = __fadd_rn(__fadd_rn(__fmul_rn(w0y, up),
                                              __fmul_rn(w1y, c[q])),
                                    __fmul_rn(w2y, dn));
            float s  = __fadd_rn(__fadd_rn(__fmul_rn(gx, gx), __fmul_rn(gy, gy)),
                                 1e-10f);
            float m  = __fmul_rn(sqrt_approx(s), gg[i]);   // continuous-effect approx
            if (m > 0.001f) {
                float o = atan2f(gy, gx);                  // bit-exact libdevice path
                if (o < 0.f) o = __fadd_rn(o, TWO_PI_F);   // jnp.mod(ori, 2pi)
                float ob = __fdiv_rn(__fmul_rn(36.f, o), TWO_PI_F);
                float bf = floorf(ob);
                int b = (int)bf;
                if (b > NBINS - 1) b -= NBINS;             // ob == 36.0 edge
                float wgt = __fmul_rn(__fsub_rn(1.f, __fsub_rn(ob, bf)), m);
                int a = b * 32 + l;                        // bank = lane
                hist[a] = __fadd_rn(hist[a], wgt);
            }
        }
    }
    __syncwarp();

    // ---- per-lane bin sums (diagonal reads, conflict-free) ----
    float s = 0.f, e = 0.f;
    #pragma unroll
    for (int cc = 0; cc < 32; ++cc)
        s = __fadd_rn(s, hist[(l << 5) + ((l + cc) & 31)]);
    if (l < 4) {
        #pragma unroll
        for (int cc = 0; cc < 32; ++cc)
            e = __fadd_rn(e, hist[((32 + l) << 5) + ((l + cc) & 31)]);
    }
    s = __fmul_rn(s, 0.0009765625f);    // /1024 exact
    e = __fmul_rn(e, 0.0009765625f);

    // ---- smoothing + first-index argmax, in-warp ----
    float hm  = __shfl_up_sync(FULLM, s, 1);
    float hp  = __shfl_down_sync(FULLM, s, 1);
    float e0  = __shfl_sync(FULLM, e, 0);
    float s31 = __shfl_sync(FULLM, s, 31);
    float em  = __shfl_up_sync(FULLM, e, 1);
    float ep  = __shfl_down_sync(FULLM, e, 1);
    if (l == 0)  hm = 0.f;              // zero pad left
    if (l == 31) hp = e0;               // h[32]
    float v1 = __fadd_rn(__fadd_rn(__fmul_rn(m0, hm), __fmul_rn(m1, s)),
                         __fmul_rn(m2, hp));
    int i1 = l;
    if (l < 4) {                        // bins 32..35
        float hm2 = (l == 0) ? s31 : em;
        float hp2 = (l == 3) ? 0.f : ep;
        float v2 = __fadd_rn(__fadd_rn(__fmul_rn(m0, hm2), __fmul_rn(m1, e)),
                             __fmul_rn(m2, hp2));
        if (v2 > v1) { v1 = v2; i1 = 32 + l; }   // tie keeps smaller index
    }
    #pragma unroll
    for (int off = 16; off > 0; off >>= 1) {
        float ov = __shfl_xor_sync(FULLM, v1, off);
        int   oi = __shfl_xor_sync(FULLM, i1, off);
        if (ov > v1 || (ov == v1 && oi < i1)) { v1 = ov; i1 = oi; }
    }
    if (l == 0) {
        float fi = (float)i1;
        out[p] = -__fsub_rn(__fdiv_rn(__fmul_rn(TWO_PI_F, fi), 36.f), PI_F);
    }
}

extern "C" void kernel_launch(void* const* d_in, const int* in_sizes, int n_in,
                              void* d_out, int out_size)
{
    const float* x   = (const float*)d_in[0];
    const float* gxw = (const float*)d_in[1];
    const float* gyw = (const float*)d_in[2];
    const float* smw = (const float*)d_in[3];
    const float* gk  = (const float*)d_in[4];
    float* out = (float*)d_out;

    int B = in_sizes[0] / (PS * PS);
    int grid = (B + 3) / 4;
    OrientationFinder_83193516523885_kernel<<<grid, BLK>>>(x, gxw, gyw, smw, gk, out, B);
}